// round 16
// baseline (speedup 1.0000x reference)
#include <cuda_runtime.h>
#include <cuda_fp16.h>
#include <mma.h>

using namespace nvcuda;

#define NMAX 100000
#define EMAX 1600000
#define CIN  128

// ---------------- scratch (device globals; no allocation allowed) ----------
__device__ int   g_deg[NMAX];          // IN-degree; zero at entry (self-cleaned)
__device__ int   g_offs[NMAX];
__device__ int   g_cursor[NMAX];
__device__ int   g_base;
__device__ __align__(16) int2   g_csr[EMAX];        // {src, float bits of dinv[src]}
__device__ __align__(16) __half g_h[NMAX * 64];     // gemm output, fp16
__device__ __align__(16) __half g_out_h[NMAX * 64]; // agg output, fp16, RELU'd

// ---------------- prep -------------------------------------------------------
__global__ void k_count(const int* __restrict__ ei, int E) {
    int i = blockIdx.x * blockDim.x + threadIdx.x;
    int e4 = i * 4;
    if (e4 >= E) return;
    if (e4 + 4 <= E) {
        int4 d = *(const int4*)&ei[E + e4];
        atomicAdd(&g_deg[d.x], 1);
        atomicAdd(&g_deg[d.y], 1);
        atomicAdd(&g_deg[d.z], 1);
        atomicAdd(&g_deg[d.w], 1);
    } else {
        for (int e = e4; e < E; e++) atomicAdd(&g_deg[ei[E + e]], 1);
    }
}

__global__ void k_scan(int n) {
    __shared__ int wsum[8];
    __shared__ int sbase;
    int t = threadIdx.x;
    int lane = t & 31, wid = t >> 5;
    int base = blockIdx.x * 1024;
    int loc[4];
    int v = 0;
    #pragma unroll
    for (int j = 0; j < 4; j++) {
        int i = base + t * 4 + j;
        loc[j] = (i < n) ? g_deg[i] : 0;
        v += loc[j];
    }
    int s = v;
    #pragma unroll
    for (int off = 1; off < 32; off <<= 1) {
        int y = __shfl_up_sync(0xffffffffu, s, off);
        if (lane >= off) s += y;
    }
    if (lane == 31) wsum[wid] = s;
    __syncthreads();
    if (t == 0) {
        int acc = 0;
        #pragma unroll
        for (int w = 0; w < 8; w++) { int x2 = wsum[w]; wsum[w] = acc; acc += x2; }
        sbase = atomicAdd(&g_base, acc);
    }
    __syncthreads();
    int run = sbase + wsum[wid] + s - v;
    #pragma unroll
    for (int j = 0; j < 4; j++) {
        int i = base + t * 4 + j;
        if (i < n) {
            g_offs[i] = run;
            g_cursor[i] = run;
            run += loc[j];
        }
    }
}

__global__ void k_fill_csr(const int* __restrict__ ei, int E) {
    int i = blockIdx.x * blockDim.x + threadIdx.x;
    int e4 = i * 4;
    if (e4 >= E) return;
    if (e4 + 4 <= E) {
        int4 sv = *(const int4*)&ei[e4];
        int4 dv = *(const int4*)&ei[E + e4];
        float i0 = rsqrtf((float)(g_deg[sv.x] + 1));
        float i1 = rsqrtf((float)(g_deg[sv.y] + 1));
        float i2 = rsqrtf((float)(g_deg[sv.z] + 1));
        float i3 = rsqrtf((float)(g_deg[sv.w] + 1));
        int p0 = atomicAdd(&g_cursor[dv.x], 1);
        int p1 = atomicAdd(&g_cursor[dv.y], 1);
        int p2 = atomicAdd(&g_cursor[dv.z], 1);
        int p3 = atomicAdd(&g_cursor[dv.w], 1);
        g_csr[p0] = make_int2(sv.x, __float_as_int(i0));
        g_csr[p1] = make_int2(sv.y, __float_as_int(i1));
        g_csr[p2] = make_int2(sv.z, __float_as_int(i2));
        g_csr[p3] = make_int2(sv.w, __float_as_int(i3));
    } else {
        for (int e = e4; e < E; e++) {
            int s = ei[e];
            int d = ei[E + e];
            float ds = rsqrtf((float)(g_deg[s] + 1));
            int pos = atomicAdd(&g_cursor[d], 1);
            g_csr[pos] = make_int2(s, __float_as_int(ds));
        }
    }
}

// ---------------- wmma GEMM -------------------------------------------------
// g_h(fp16) = A @ W,  A = x(fp32->fp16) [SRC_F32] or g_out_h(fp16).
// A tiles in smem fp16, W fp16 in smem, fp32 accum, 16x16 smem out-staging.
// 256 threads = 8 warps. BM/16 row-tiles; warps split N into NWARP/(BM/16) parts.
template <int K, int COUTP, int COUTR, bool SRC_F32, int BM>
__global__ __launch_bounds__(256)
void k_gemm_wmma(const float* __restrict__ X, const float* __restrict__ W, int n) {
    constexpr int NWARP = 8;
    constexpr int ROWT = BM / 16;                  // row tiles per block
    constexpr int NSPLIT = NWARP / ROWT;           // warps sharing a row tile
    constexpr int NCW = COUTP / 16 / NSPLIT;       // n-tiles per warp
    __shared__ __half ws[K][COUTP];
    __shared__ __half xs[BM][K];
    __shared__ float  stage[NWARP][16][16];

    int t = threadIdx.x;
    int warp = t >> 5, lane = t & 31;

    // load W -> fp16 smem (zero-pad COUTP > COUTR)
    for (int idx = t; idx < K * COUTP; idx += 256) ws[idx / COUTP][idx % COUTP] = __float2half(0.f);
    __syncthreads();
    for (int idx = t; idx < K * COUTR; idx += 256) {
        int k = idx / COUTR, c = idx % COUTR;
        ws[k][c] = __float2half(W[idx]);
    }

    int rowt = warp % ROWT;                        // this warp's 16-row tile
    int nbase = (warp / ROWT) * NCW;               // first n-tile
    int ntiles = (n + BM - 1) / BM;

    for (int tile = blockIdx.x; tile < ntiles; tile += gridDim.x) {
        int base = tile * BM;
        __syncthreads();
        // load A tile
        constexpr int XF4 = BM * K / 4;
        for (int idx = t; idx < XF4; idx += 256) {
            int r = idx / (K / 4), kc = idx % (K / 4);
            int gr = base + r;
            if (SRC_F32) {
                float4 v = make_float4(0.f, 0.f, 0.f, 0.f);
                if (gr < n) v = *(const float4*)&X[(size_t)gr * K + kc * 4];
                __half2 p0 = __floats2half2_rn(v.x, v.y);
                __half2 p1 = __floats2half2_rn(v.z, v.w);
                *(uint2*)&xs[r][kc * 4] = make_uint2(*(unsigned*)&p0, *(unsigned*)&p1);
            } else {
                uint2 u = make_uint2(0u, 0u);
                if (gr < n) u = *(const uint2*)&g_out_h[(size_t)gr * K + kc * 4];
                *(uint2*)&xs[r][kc * 4] = u;
            }
        }
        __syncthreads();

        int rowbase = base + rowt * 16;
        #pragma unroll
        for (int nc = 0; nc < NCW; nc++) {
            int ncol = (nbase + nc) * 16;
            wmma::fragment<wmma::accumulator, 16, 16, 16, float> acc;
            wmma::fill_fragment(acc, 0.f);
            #pragma unroll
            for (int kt = 0; kt < K / 16; kt++) {
                wmma::fragment<wmma::matrix_a, 16, 16, 16, __half, wmma::row_major> a;
                wmma::fragment<wmma::matrix_b, 16, 16, 16, __half, wmma::row_major> b;
                wmma::load_matrix_sync(a, &xs[rowt * 16][kt * 16], K);
                wmma::load_matrix_sync(b, &ws[kt * 16][ncol], COUTP);
                wmma::mma_sync(acc, a, b, acc);
            }
            wmma::store_matrix_sync(&stage[warp][0][0], acc, 16, wmma::mem_row_major);
            __syncwarp();
            // write 16x16 fp32 stage -> fp16 g_h (lane does 4 half2)
            #pragma unroll
            for (int j = 0; j < 4; j++) {
                int i2 = lane * 4 + j;           // 0..127 half2 slots
                int r = i2 >> 3, c2 = (i2 & 7) * 2;
                int gr = rowbase + r;
                int gc = ncol + c2;
                if (gr < n && gc < COUTR) {
                    __half2 p = __floats2half2_rn(stage[warp][r][c2], stage[warp][r][c2 + 1]);
                    *(unsigned*)&g_h[(size_t)gr * COUTR + gc] = *(unsigned*)&p;
                }
            }
            __syncwarp();
        }
    }
}

// ---------------- aggregation C=64 (layers 1/2), half-warp split -------------
__global__ void k_agg64(const float* __restrict__ b, int n) {
    const __half* H = (const __half*)g_h;

    int node = (blockIdx.x * blockDim.x + threadIdx.x) >> 5;
    int lane = threadIdx.x & 31;
    if (node >= n) return;
    int half = lane >> 4;
    int c = (lane & 15) * 4;

    int indeg = g_deg[node];
    float dinv = rsqrtf((float)(indeg + 1));

    float a0, a1, a2, a3;
    {
        uint2 u = *(const uint2*)&H[(size_t)node * 64 + c];
        float2 f01 = __half22float2(*(__half2*)&u.x);
        float2 f23 = __half22float2(*(__half2*)&u.y);
        float w0 = half ? 0.f : dinv;
        a0 = w0 * f01.x; a1 = w0 * f01.y; a2 = w0 * f23.x; a3 = w0 * f23.y;
    }

    int e0 = g_offs[node];
    int e1 = e0 + indeg;
    int e = e0;
    for (; e + 8 <= e1; e += 8) {
        #pragma unroll
        for (int j = 0; j < 4; j++) {
            int2 r = g_csr[e + j * 2 + half];
            float nr = __int_as_float(r.y);
            uint2 u = *(const uint2*)&H[(size_t)r.x * 64 + c];
            float2 g01 = __half22float2(*(__half2*)&u.x);
            float2 g23 = __half22float2(*(__half2*)&u.y);
            a0 += nr * g01.x; a1 += nr * g01.y;
            a2 += nr * g23.x; a3 += nr * g23.y;
        }
    }
    for (; e < e1; e += 2) {
        int idx = e + half;
        int2 r = (idx < e1) ? g_csr[idx] : make_int2(node, 0);
        float nr = __int_as_float(r.y);
        uint2 u = *(const uint2*)&H[(size_t)r.x * 64 + c];
        float2 g01 = __half22float2(*(__half2*)&u.x);
        float2 g23 = __half22float2(*(__half2*)&u.y);
        a0 += nr * g01.x; a1 += nr * g01.y;
        a2 += nr * g23.x; a3 += nr * g23.y;
    }

    a0 += __shfl_xor_sync(0xffffffffu, a0, 16);
    a1 += __shfl_xor_sync(0xffffffffu, a1, 16);
    a2 += __shfl_xor_sync(0xffffffffu, a2, 16);
    a3 += __shfl_xor_sync(0xffffffffu, a3, 16);

    if (half == 0) {
        float o0 = fmaxf(b[c]     + dinv * a0, 0.f);
        float o1 = fmaxf(b[c + 1] + dinv * a1, 0.f);
        float o2 = fmaxf(b[c + 2] + dinv * a2, 0.f);
        float o3 = fmaxf(b[c + 3] + dinv * a3, 0.f);
        __half2 p0 = __floats2half2_rn(o0, o1);
        __half2 p1 = __floats2half2_rn(o2, o3);
        uint2 u = make_uint2(*(unsigned*)&p0, *(unsigned*)&p1);
        *(uint2*)&g_out_h[(size_t)node * 64 + c] = u;
    }
}

// ---------------- final aggregation (C=40, fp32 out, self-clean) -------------
__global__ void k_agg_final(const float* __restrict__ b, float* __restrict__ OUT,
                            int n) {
    constexpr int C = 40;
    const __half* H = (const __half*)g_h;

    int node = (blockIdx.x * blockDim.x + threadIdx.x) >> 5;
    int lane = threadIdx.x & 31;
    if (node >= n) return;
    int c = lane * 2;
    bool act = (c < C);

    int indeg = g_deg[node];
    float dinv = rsqrtf((float)(indeg + 1));

    float2 acc = make_float2(0.f, 0.f);
    if (act) {
        float2 hv = __half22float2(*(const __half2*)&H[(size_t)node * C + c]);
        acc.x = dinv * hv.x;
        acc.y = dinv * hv.y;
    }

    int e0 = g_offs[node];
    int e1 = e0 + indeg;
    int e = e0;
    for (; e + 4 <= e1; e += 4) {
        int2 r0 = g_csr[e];
        int2 r1 = g_csr[e + 1];
        int2 r2 = g_csr[e + 2];
        int2 r3 = g_csr[e + 3];
        if (act) {
            float2 h0 = __half22float2(*(const __half2*)&H[(size_t)r0.x * C + c]);
            float2 h1 = __half22float2(*(const __half2*)&H[(size_t)r1.x * C + c]);
            float2 h2 = __half22float2(*(const __half2*)&H[(size_t)r2.x * C + c]);
            float2 h3 = __half22float2(*(const __half2*)&H[(size_t)r3.x * C + c]);
            float n0 = __int_as_float(r0.y), n1 = __int_as_float(r1.y);
            float n2 = __int_as_float(r2.y), n3 = __int_as_float(r3.y);
            acc.x += n0 * h0.x; acc.y += n0 * h0.y;
            acc.x += n1 * h1.x; acc.y += n1 * h1.y;
            acc.x += n2 * h2.x; acc.y += n2 * h2.y;
            acc.x += n3 * h3.x; acc.y += n3 * h3.y;
        }
    }
    for (; e < e1; e++) {
        int2 r = g_csr[e];
        if (act) {
            float2 hv = __half22float2(*(const __half2*)&H[(size_t)r.x * C + c]);
            float nn = __int_as_float(r.y);
            acc.x += nn * hv.x; acc.y += nn * hv.y;
        }
    }
    if (act) {
        float ox = b[c]     + dinv * acc.x;
        float oy = b[c + 1] + dinv * acc.y;
        *(float2*)&OUT[(size_t)node * C + c] = make_float2(ox, oy);
    }
    if (lane == 0) g_deg[node] = 0;
    if (node == 0 && lane == 1) g_base = 0;
}

// ---------------- launcher ---------------------------------------------------
extern "C" void kernel_launch(void* const* d_in, const int* in_sizes, int n_in,
                              void* d_out, int out_size) {
    const float* x  = (const float*)d_in[0];
    const int*   ei = (const int*)d_in[1];
    const float* W1 = (const float*)d_in[2];
    const float* b1 = (const float*)d_in[3];
    const float* W2 = (const float*)d_in[4];
    const float* b2 = (const float*)d_in[5];
    const float* W3 = (const float*)d_in[6];
    const float* b3 = (const float*)d_in[7];
    float* out = (float*)d_out;

    int n = in_sizes[0] / CIN;
    int E = in_sizes[1] / 2;
    if (n > NMAX) n = NMAX;
    if (E > EMAX) E = EMAX;
    int nb = (n + 1023) / 1024;
    int eb4 = ((E + 3) / 4 + 255) / 256;

    static cudaStream_t s2 = nullptr;
    static cudaEvent_t evFork = nullptr, evJoin = nullptr;
    if (!s2) {
        cudaStreamCreate(&s2);
        cudaEventCreateWithFlags(&evFork, cudaEventDisableTiming);
        cudaEventCreateWithFlags(&evJoin, cudaEventDisableTiming);
    }

    cudaEventRecord(evFork, 0);
    cudaStreamWaitEvent(s2, evFork, 0);

    k_count<<<eb4, 256, 0, s2>>>(ei, E);
    k_scan<<<nb, 256, 0, s2>>>(n);
    k_fill_csr<<<eb4, 256, 0, s2>>>(ei, E);
    cudaEventRecord(evJoin, s2);

    // layer 1 GEMM: x[128] -> 64, wmma (BM=64: 4 row tiles x 2 N-splits)
    k_gemm_wmma<128, 64, 64, true, 64><<<592, 256>>>(x, W1, n);

    cudaStreamWaitEvent(0, evJoin, 0);

    int agg_grid = (n + 7) / 8;

    k_agg64<<<agg_grid, 256>>>(b1, n);
    k_gemm_wmma<64, 64, 64, false, 128><<<592, 256>>>(nullptr, W2, n);
    k_agg64<<<agg_grid, 256>>>(b2, n);
    k_gemm_wmma<64, 48, 40, false, 128><<<592, 256>>>(nullptr, W3, n);
    k_agg_final<<<agg_grid, 256>>>(b3, out, n);
}

// round 17
// speedup vs baseline: 1.2048x; 1.2048x over previous
#include <cuda_runtime.h>
#include <cuda_fp16.h>

#define NMAX 100000
#define EMAX 1600000
#define CIN  128

// ---------------- scratch (device globals; no allocation allowed) ----------
__device__ int   g_deg[NMAX];          // IN-degree; zero at entry (self-cleaned)
__device__ int   g_offs[NMAX];
__device__ int   g_cursor[NMAX];
__device__ int   g_base;
__device__ __align__(16) int2   g_csr[EMAX];        // {src, float bits of dinv[src]}
__device__ __align__(16) __half g_h[NMAX * 64];     // gemm output, fp16
__device__ __align__(16) __half g_out_h[NMAX * 64]; // agg output, fp16, RELU'd

// ---------------- prep -------------------------------------------------------
__global__ void k_count(const int* __restrict__ ei, int E) {
    int i = blockIdx.x * blockDim.x + threadIdx.x;
    int e4 = i * 4;
    if (e4 >= E) return;
    if (e4 + 4 <= E) {
        int4 d = *(const int4*)&ei[E + e4];
        atomicAdd(&g_deg[d.x], 1);
        atomicAdd(&g_deg[d.y], 1);
        atomicAdd(&g_deg[d.z], 1);
        atomicAdd(&g_deg[d.w], 1);
    } else {
        for (int e = e4; e < E; e++) atomicAdd(&g_deg[ei[E + e]], 1);
    }
}

__global__ void k_scan(int n) {
    __shared__ int wsum[8];
    __shared__ int sbase;
    int t = threadIdx.x;
    int lane = t & 31, wid = t >> 5;
    int base = blockIdx.x * 1024;
    int loc[4];
    int v = 0;
    #pragma unroll
    for (int j = 0; j < 4; j++) {
        int i = base + t * 4 + j;
        loc[j] = (i < n) ? g_deg[i] : 0;
        v += loc[j];
    }
    int s = v;
    #pragma unroll
    for (int off = 1; off < 32; off <<= 1) {
        int y = __shfl_up_sync(0xffffffffu, s, off);
        if (lane >= off) s += y;
    }
    if (lane == 31) wsum[wid] = s;
    __syncthreads();
    if (t == 0) {
        int acc = 0;
        #pragma unroll
        for (int w = 0; w < 8; w++) { int x2 = wsum[w]; wsum[w] = acc; acc += x2; }
        sbase = atomicAdd(&g_base, acc);
    }
    __syncthreads();
    int run = sbase + wsum[wid] + s - v;
    #pragma unroll
    for (int j = 0; j < 4; j++) {
        int i = base + t * 4 + j;
        if (i < n) {
            g_offs[i] = run;
            g_cursor[i] = run;
            run += loc[j];
        }
    }
}

__global__ void k_fill_csr(const int* __restrict__ ei, int E) {
    int i = blockIdx.x * blockDim.x + threadIdx.x;
    int e4 = i * 4;
    if (e4 >= E) return;
    if (e4 + 4 <= E) {
        int4 sv = *(const int4*)&ei[e4];
        int4 dv = *(const int4*)&ei[E + e4];
        float i0 = rsqrtf((float)(g_deg[sv.x] + 1));
        float i1 = rsqrtf((float)(g_deg[sv.y] + 1));
        float i2 = rsqrtf((float)(g_deg[sv.z] + 1));
        float i3 = rsqrtf((float)(g_deg[sv.w] + 1));
        int p0 = atomicAdd(&g_cursor[dv.x], 1);
        int p1 = atomicAdd(&g_cursor[dv.y], 1);
        int p2 = atomicAdd(&g_cursor[dv.z], 1);
        int p3 = atomicAdd(&g_cursor[dv.w], 1);
        g_csr[p0] = make_int2(sv.x, __float_as_int(i0));
        g_csr[p1] = make_int2(sv.y, __float_as_int(i1));
        g_csr[p2] = make_int2(sv.z, __float_as_int(i2));
        g_csr[p3] = make_int2(sv.w, __float_as_int(i3));
    } else {
        for (int e = e4; e < E; e++) {
            int s = ei[e];
            int d = ei[E + e];
            float ds = rsqrtf((float)(g_deg[s] + 1));
            int pos = atomicAdd(&g_cursor[d], 1);
            g_csr[pos] = make_int2(s, __float_as_int(ds));
        }
    }
}

// ---------------- layer-1 GEMM (BM=64, 256 thr, fp16 X-tile) -----------------
__global__ __launch_bounds__(256, 4)
void k_gemm1(const float* __restrict__ X, const float* __restrict__ W, int n) {
    constexpr int K = 128, COUT = 64, BM = 64;
    constexpr int NT = COUT / 4;
    constexpr int NTHREADS = 256;
    __shared__ float  ws[K][COUT];
    __shared__ __half xs[BM][K];

    int t = threadIdx.x;
    constexpr int WF4 = K * COUT / 4;
    float* wsf = &ws[0][0];
    for (int idx = t; idx < WF4; idx += NTHREADS)
        *(float4*)&wsf[idx * 4] = *(const float4*)&W[idx * 4];

    int nidx = t % NT;
    int midx = t / NT;
    int ntiles = (n + BM - 1) / BM;

    for (int tile = blockIdx.x; tile < ntiles; tile += gridDim.x) {
        int base = tile * BM;
        __syncthreads();
        constexpr int XF4 = BM * K / 4;
        for (int idx = t; idx < XF4; idx += NTHREADS) {
            int r = idx / (K / 4), kc = idx % (K / 4);
            int gr = base + r;
            float4 v = make_float4(0.f, 0.f, 0.f, 0.f);
            if (gr < n) v = *(const float4*)&X[(size_t)gr * K + kc * 4];
            __half2 p0 = __floats2half2_rn(v.x, v.y);
            __half2 p1 = __floats2half2_rn(v.z, v.w);
            *(uint2*)&xs[r][kc * 4] = make_uint2(*(unsigned*)&p0, *(unsigned*)&p1);
        }
        __syncthreads();

        float acc[4][4] = {};
        #pragma unroll 4
        for (int k4 = 0; k4 < K / 4; k4++) {
            uint2 ar[4];
            #pragma unroll
            for (int i = 0; i < 4; i++)
                ar[i] = *(const uint2*)&xs[midx * 4 + i][k4 * 4];
            float a[4][4];
            #pragma unroll
            for (int i = 0; i < 4; i++) {
                float2 f01 = __half22float2(*(__half2*)&ar[i].x);
                float2 f23 = __half22float2(*(__half2*)&ar[i].y);
                a[i][0] = f01.x; a[i][1] = f01.y; a[i][2] = f23.x; a[i][3] = f23.y;
            }
            #pragma unroll
            for (int kk = 0; kk < 4; kk++) {
                float4 b4 = *(const float4*)&ws[k4 * 4 + kk][nidx * 4];
                #pragma unroll
                for (int i = 0; i < 4; i++) {
                    acc[i][0] += a[i][kk] * b4.x;
                    acc[i][1] += a[i][kk] * b4.y;
                    acc[i][2] += a[i][kk] * b4.z;
                    acc[i][3] += a[i][kk] * b4.w;
                }
            }
        }

        #pragma unroll
        for (int i = 0; i < 4; i++) {
            int gr = base + midx * 4 + i;
            if (gr < n) {
                __half2 p0 = __floats2half2_rn(acc[i][0], acc[i][1]);
                __half2 p1 = __floats2half2_rn(acc[i][2], acc[i][3]);
                uint2 u = make_uint2(*(unsigned*)&p0, *(unsigned*)&p1);
                *(uint2*)&g_h[(size_t)gr * COUT + nidx * 4] = u;
            }
        }
    }
}

// ---------------- layers 2/3 GEMM (fp16 X-tile passthrough) ------------------
template <int K, int COUT>
__global__ void k_gemm_h(const float* __restrict__ W, int n) {
    constexpr int BM = 64;
    constexpr int NT = COUT / 4;
    constexpr int MT = BM / 4;
    constexpr int NTHREADS = NT * MT;
    __shared__ float  ws[K][COUT];
    __shared__ __half xs[BM][K];

    int t = threadIdx.x;
    constexpr int WF4 = K * COUT / 4;
    float* wsf = &ws[0][0];
    for (int idx = t; idx < WF4; idx += NTHREADS)
        *(float4*)&wsf[idx * 4] = *(const float4*)&W[idx * 4];

    int nidx = t % NT;
    int midx = t / NT;
    int ntiles = (n + BM - 1) / BM;

    for (int tile = blockIdx.x; tile < ntiles; tile += gridDim.x) {
        int base = tile * BM;
        __syncthreads();
        constexpr int XF4 = BM * K / 4;
        for (int idx = t; idx < XF4; idx += NTHREADS) {
            int r = idx / (K / 4), kc = idx % (K / 4);
            int gr = base + r;
            uint2 u = make_uint2(0u, 0u);
            if (gr < n) u = *(const uint2*)&g_out_h[(size_t)gr * K + kc * 4];
            *(uint2*)&xs[r][kc * 4] = u;
        }
        __syncthreads();

        float acc[4][4] = {};
        #pragma unroll 4
        for (int k4 = 0; k4 < K / 4; k4++) {
            uint2 ar[4];
            #pragma unroll
            for (int i = 0; i < 4; i++)
                ar[i] = *(const uint2*)&xs[midx * 4 + i][k4 * 4];
            float a[4][4];
            #pragma unroll
            for (int i = 0; i < 4; i++) {
                float2 f01 = __half22float2(*(__half2*)&ar[i].x);
                float2 f23 = __half22float2(*(__half2*)&ar[i].y);
                a[i][0] = f01.x; a[i][1] = f01.y; a[i][2] = f23.x; a[i][3] = f23.y;
            }
            #pragma unroll
            for (int kk = 0; kk < 4; kk++) {
                float4 b4 = *(const float4*)&ws[k4 * 4 + kk][nidx * 4];
                #pragma unroll
                for (int i = 0; i < 4; i++) {
                    acc[i][0] += a[i][kk] * b4.x;
                    acc[i][1] += a[i][kk] * b4.y;
                    acc[i][2] += a[i][kk] * b4.z;
                    acc[i][3] += a[i][kk] * b4.w;
                }
            }
        }

        #pragma unroll
        for (int i = 0; i < 4; i++) {
            int gr = base + midx * 4 + i;
            if (gr < n) {
                __half2 p0 = __floats2half2_rn(acc[i][0], acc[i][1]);
                __half2 p1 = __floats2half2_rn(acc[i][2], acc[i][3]);
                uint2 u = make_uint2(*(unsigned*)&p0, *(unsigned*)&p1);
                *(uint2*)&g_h[(size_t)gr * COUT + nidx * 4] = u;
            }
        }
    }
}

// ---------------- aggregation C=64, 2 nodes/warp, half-warp split ------------
// Per iteration: 4 independent csr LDG + 4 independent gather LDG = 8 edges.
// Out-of-range slots read {node, 0} (self row x 0, L1-hot).
__global__ void k_agg64(const float* __restrict__ b, int n) {
    const __half* H = (const __half*)g_h;

    int warp = (blockIdx.x * blockDim.x + threadIdx.x) >> 5;
    int lane = threadIdx.x & 31;
    int nodeA = warp * 2;
    int nodeB = warp * 2 + 1;
    if (nodeA >= n) return;
    bool hasB = (nodeB < n);
    int half = lane >> 4;
    int c = (lane & 15) * 4;

    int degA = g_deg[nodeA];
    int degB = hasB ? g_deg[nodeB] : 0;
    float dinvA = rsqrtf((float)(degA + 1));
    float dinvB = rsqrtf((float)(degB + 1));

    float aA0, aA1, aA2, aA3, aB0 = 0.f, aB1 = 0.f, aB2 = 0.f, aB3 = 0.f;
    {
        uint2 u = *(const uint2*)&H[(size_t)nodeA * 64 + c];
        float2 f01 = __half22float2(*(__half2*)&u.x);
        float2 f23 = __half22float2(*(__half2*)&u.y);
        float w0 = half ? 0.f : dinvA;
        aA0 = w0 * f01.x; aA1 = w0 * f01.y; aA2 = w0 * f23.x; aA3 = w0 * f23.y;
    }
    if (hasB) {
        uint2 u = *(const uint2*)&H[(size_t)nodeB * 64 + c];
        float2 f01 = __half22float2(*(__half2*)&u.x);
        float2 f23 = __half22float2(*(__half2*)&u.y);
        float w0 = half ? 0.f : dinvB;
        aB0 = w0 * f01.x; aB1 = w0 * f01.y; aB2 = w0 * f23.x; aB3 = w0 * f23.y;
    }

    int eA = g_offs[nodeA], e1A = eA + degA;
    int eB = hasB ? g_offs[nodeB] : 0, e1B = eB + degB;

    while (eA < e1A || eB < e1B) {
        // 4 csr loads (2 per node), independent
        int iA0 = eA + half,     iA1 = eA + 2 + half;
        int iB0 = eB + half,     iB1 = eB + 2 + half;
        int2 rA0 = (iA0 < e1A) ? g_csr[iA0] : make_int2(nodeA, 0);
        int2 rA1 = (iA1 < e1A) ? g_csr[iA1] : make_int2(nodeA, 0);
        int2 rB0 = (iB0 < e1B) ? g_csr[iB0] : make_int2(nodeA, 0);
        int2 rB1 = (iB1 < e1B) ? g_csr[iB1] : make_int2(nodeA, 0);
        // 4 gathers, independent
        uint2 uA0 = *(const uint2*)&H[(size_t)rA0.x * 64 + c];
        uint2 uA1 = *(const uint2*)&H[(size_t)rA1.x * 64 + c];
        uint2 uB0 = *(const uint2*)&H[(size_t)rB0.x * 64 + c];
        uint2 uB1 = *(const uint2*)&H[(size_t)rB1.x * 64 + c];

        float nA0 = __int_as_float(rA0.y), nA1 = __int_as_float(rA1.y);
        float nB0 = __int_as_float(rB0.y), nB1 = __int_as_float(rB1.y);
        {
            float2 g01 = __half22float2(*(__half2*)&uA0.x);
            float2 g23 = __half22float2(*(__half2*)&uA0.y);
            aA0 += nA0 * g01.x; aA1 += nA0 * g01.y; aA2 += nA0 * g23.x; aA3 += nA0 * g23.y;
        }
        {
            float2 g01 = __half22float2(*(__half2*)&uA1.x);
            float2 g23 = __half22float2(*(__half2*)&uA1.y);
            aA0 += nA1 * g01.x; aA1 += nA1 * g01.y; aA2 += nA1 * g23.x; aA3 += nA1 * g23.y;
        }
        {
            float2 g01 = __half22float2(*(__half2*)&uB0.x);
            float2 g23 = __half22float2(*(__half2*)&uB0.y);
            aB0 += nB0 * g01.x; aB1 += nB0 * g01.y; aB2 += nB0 * g23.x; aB3 += nB0 * g23.y;
        }
        {
            float2 g01 = __half22float2(*(__half2*)&uB1.x);
            float2 g23 = __half22float2(*(__half2*)&uB1.y);
            aB0 += nB1 * g01.x; aB1 += nB1 * g01.y; aB2 += nB1 * g23.x; aB3 += nB1 * g23.y;
        }
        eA += 4;
        eB += 4;
    }

    aA0 += __shfl_xor_sync(0xffffffffu, aA0, 16);
    aA1 += __shfl_xor_sync(0xffffffffu, aA1, 16);
    aA2 += __shfl_xor_sync(0xffffffffu, aA2, 16);
    aA3 += __shfl_xor_sync(0xffffffffu, aA3, 16);
    aB0 += __shfl_xor_sync(0xffffffffu, aB0, 16);
    aB1 += __shfl_xor_sync(0xffffffffu, aB1, 16);
    aB2 += __shfl_xor_sync(0xffffffffu, aB2, 16);
    aB3 += __shfl_xor_sync(0xffffffffu, aB3, 16);

    if (half == 0) {
        {
            float o0 = fmaxf(b[c]     + dinvA * aA0, 0.f);
            float o1 = fmaxf(b[c + 1] + dinvA * aA1, 0.f);
            float o2 = fmaxf(b[c + 2] + dinvA * aA2, 0.f);
            float o3 = fmaxf(b[c + 3] + dinvA * aA3, 0.f);
            __half2 p0 = __floats2half2_rn(o0, o1);
            __half2 p1 = __floats2half2_rn(o2, o3);
            uint2 u = make_uint2(*(unsigned*)&p0, *(unsigned*)&p1);
            *(uint2*)&g_out_h[(size_t)nodeA * 64 + c] = u;
        }
        if (hasB) {
            float o0 = fmaxf(b[c]     + dinvB * aB0, 0.f);
            float o1 = fmaxf(b[c + 1] + dinvB * aB1, 0.f);
            float o2 = fmaxf(b[c + 2] + dinvB * aB2, 0.f);
            float o3 = fmaxf(b[c + 3] + dinvB * aB3, 0.f);
            __half2 p0 = __floats2half2_rn(o0, o1);
            __half2 p1 = __floats2half2_rn(o2, o3);
            uint2 u = make_uint2(*(unsigned*)&p0, *(unsigned*)&p1);
            *(uint2*)&g_out_h[(size_t)nodeB * 64 + c] = u;
        }
    }
}

// ---------------- final aggregation (C=40, fp32 out, self-clean) -------------
__global__ void k_agg_final(const float* __restrict__ b, float* __restrict__ OUT,
                            int n) {
    constexpr int C = 40;
    const __half* H = (const __half*)g_h;

    int node = (blockIdx.x * blockDim.x + threadIdx.x) >> 5;
    int lane = threadIdx.x & 31;
    if (node >= n) return;
    int c = lane * 2;
    bool act = (c < C);

    int indeg = g_deg[node];
    float dinv = rsqrtf((float)(indeg + 1));

    float2 acc = make_float2(0.f, 0.f);
    if (act) {
        float2 hv = __half22float2(*(const __half2*)&H[(size_t)node * C + c]);
        acc.x = dinv * hv.x;
        acc.y = dinv * hv.y;
    }

    int e0 = g_offs[node];
    int e1 = e0 + indeg;
    int e = e0;
    for (; e + 4 <= e1; e += 4) {
        int2 r0 = g_csr[e];
        int2 r1 = g_csr[e + 1];
        int2 r2 = g_csr[e + 2];
        int2 r3 = g_csr[e + 3];
        if (act) {
            float2 h0 = __half22float2(*(const __half2*)&H[(size_t)r0.x * C + c]);
            float2 h1 = __half22float2(*(const __half2*)&H[(size_t)r1.x * C + c]);
            float2 h2 = __half22float2(*(const __half2*)&H[(size_t)r2.x * C + c]);
            float2 h3 = __half22float2(*(const __half2*)&H[(size_t)r3.x * C + c]);
            float n0 = __int_as_float(r0.y), n1 = __int_as_float(r1.y);
            float n2 = __int_as_float(r2.y), n3 = __int_as_float(r3.y);
            acc.x += n0 * h0.x; acc.y += n0 * h0.y;
            acc.x += n1 * h1.x; acc.y += n1 * h1.y;
            acc.x += n2 * h2.x; acc.y += n2 * h2.y;
            acc.x += n3 * h3.x; acc.y += n3 * h3.y;
        }
    }
    for (; e < e1; e++) {
        int2 r = g_csr[e];
        if (act) {
            float2 hv = __half22float2(*(const __half2*)&H[(size_t)r.x * C + c]);
            float nn = __int_as_float(r.y);
            acc.x += nn * hv.x; acc.y += nn * hv.y;
        }
    }
    if (act) {
        float ox = b[c]     + dinv * acc.x;
        float oy = b[c + 1] + dinv * acc.y;
        *(float2*)&OUT[(size_t)node * C + c] = make_float2(ox, oy);
    }
    if (lane == 0) g_deg[node] = 0;
    if (node == 0 && lane == 1) g_base = 0;
}

// ---------------- launcher ---------------------------------------------------
extern "C" void kernel_launch(void* const* d_in, const int* in_sizes, int n_in,
                              void* d_out, int out_size) {
    const float* x  = (const float*)d_in[0];
    const int*   ei = (const int*)d_in[1];
    const float* W1 = (const float*)d_in[2];
    const float* b1 = (const float*)d_in[3];
    const float* W2 = (const float*)d_in[4];
    const float* b2 = (const float*)d_in[5];
    const float* W3 = (const float*)d_in[6];
    const float* b3 = (const float*)d_in[7];
    float* out = (float*)d_out;

    int n = in_sizes[0] / CIN;
    int E = in_sizes[1] / 2;
    if (n > NMAX) n = NMAX;
    if (E > EMAX) E = EMAX;
    int nb = (n + 1023) / 1024;
    int eb4 = ((E + 3) / 4 + 255) / 256;

    static cudaStream_t s2 = nullptr;
    static cudaEvent_t evFork = nullptr, evJoin = nullptr;
    if (!s2) {
        cudaStreamCreate(&s2);
        cudaEventCreateWithFlags(&evFork, cudaEventDisableTiming);
        cudaEventCreateWithFlags(&evJoin, cudaEventDisableTiming);
    }

    cudaEventRecord(evFork, 0);
    cudaStreamWaitEvent(s2, evFork, 0);

    k_count<<<eb4, 256, 0, s2>>>(ei, E);
    k_scan<<<nb, 256, 0, s2>>>(n);
    k_fill_csr<<<eb4, 256, 0, s2>>>(ei, E);
    cudaEventRecord(evJoin, s2);

    k_gemm1<<<592, 256>>>(x, W1, n);

    cudaStreamWaitEvent(0, evJoin, 0);

    int agg2_grid = ((n + 1) / 2 + 7) / 8;   // 2 nodes per warp
    int agg_grid  = (n + 7) / 8;

    k_agg64<<<agg2_grid, 256>>>(b1, n);
    k_gemm_h<64, 64><<<592, 256>>>(W2, n);
    k_agg64<<<agg2_grid, 256>>>(b2, n);
    k_gemm_h<64, 40><<<592, 160>>>(W3, n);
    k_agg_final<<<agg_grid, 256>>>(b3, out, n);
}